// round 13
// baseline (speedup 1.0000x reference)
#include <cuda_runtime.h>
#include <cstdint>

// ---------------------------------------------------------------------------
// TripletLoss, single fused persistent kernel.
//   Symmetric distance: only upper-triangle 32x16 tile-jobs computed (156 of
//   them), mirror written via smem transpose. 288 blocks x 256 threads
//   (2 blocks/SM co-resident, single wave -> grid barrier safe).
//   Phase B (R12): batched candidate loads (MLP=12) + inlined threefry gumbel.
//   B=384, D=256, C=48. JAX-exact gumbel (partitionable, bits=x0^x1, key 42).
// ---------------------------------------------------------------------------

#define B 384
#define D 256
#define MARGIN 0.2f
#define TINYF 1.17549435e-38f
#define NBLK 288
#define NTHR 256
#define TI 32                         // tile rows (i)
#define TJ 16                         // tile cols (j)
#define TK 32                         // K chunk
#define PITCH 36                      // floats; 144B rows, 16B-aligned
#define NJOBS 156                     // 78 upper tiles * 2 half-jobs
#define NPAIR_MAX ((B * (B - 1)) / 2)

typedef unsigned long long u64;

// packed f32x2 helpers (Blackwell sm_103a; ptxas never emits these from C++)
#define ADD2(out, a, b) \
    asm("add.rn.f32x2 %0, %1, %2;" : "=l"(out) : "l"(a), "l"(b))
#define FMA2(acc, d) \
    asm("fma.rn.f32x2 %0, %1, %1, %0;" : "+l"(acc) : "l"(d))

// ---- persistent device state (restored to initial values every run) -------
__device__ float    g_dist[B * B];
__device__ int      g_pairlist[NPAIR_MAX];
__device__ int      g_npairs = 0;
__device__ float    g_total  = 0.0f;
__device__ int      g_count  = 0;
__device__ unsigned g_done   = 0;
__device__ unsigned g_barcnt = 0;
__device__ volatile unsigned g_sense = 0;

// ---- threefry2x32, JAX schedule, key = [0, 42] -----------------------------
__device__ __forceinline__ uint32_t rotl32(uint32_t x, int d) {
    return __funnelshift_l(x, x, d);
}

__device__ __forceinline__ float gumbel_at(uint32_t n) {
    // counter = (0, n) since n < 384^3 < 2^32 ; key = [0, 42]
    const uint32_t k0 = 0u, k1 = 42u;
    const uint32_t k2 = k0 ^ k1 ^ 0x1BD11BDAu;
    uint32_t x0 = 0u + k0, x1 = n + k1;
#define TF_RND(r) { x0 += x1; x1 = rotl32(x1, (r)); x1 ^= x0; }
    TF_RND(13) TF_RND(15) TF_RND(26) TF_RND(6)
    x0 += k1; x1 += k2 + 1u;
    TF_RND(17) TF_RND(29) TF_RND(16) TF_RND(24)
    x0 += k2; x1 += k0 + 2u;
    TF_RND(13) TF_RND(15) TF_RND(26) TF_RND(6)
    x0 += k0; x1 += k1 + 3u;
    TF_RND(17) TF_RND(29) TF_RND(16) TF_RND(24)
    x0 += k1; x1 += k2 + 4u;
    TF_RND(13) TF_RND(15) TF_RND(26) TF_RND(6)
    x0 += k2; x1 += k0 + 5u;
#undef TF_RND
    uint32_t bits = x0 ^ x1;   // partitionable 32-bit draw
    float f = __uint_as_float((bits >> 9) | 0x3f800000u) - 1.0f;
    float u = fmaxf(TINYF, f + TINYF);
    return -logf(-logf(u));
}

// ---- sense-reversing grid barrier (288 blocks, 2/SM resident, one wave) ----
__device__ __forceinline__ void grid_barrier() {
    __syncthreads();
    __threadfence();
    if (threadIdx.x == 0) {
        unsigned s = g_sense;
        if (atomicAdd(&g_barcnt, 1u) == gridDim.x - 1) {
            atomicExch(&g_barcnt, 0u);
            __threadfence();
            g_sense = s ^ 1u;
        } else {
            while (g_sense == s) { }
        }
    }
    __syncthreads();
}

// ---- the fused kernel --------------------------------------------------------
__global__ void __launch_bounds__(NTHR)
k_fused(const float* __restrict__ f, const int* __restrict__ labels,
        const int* __restrict__ epoch, float* __restrict__ out) {
    __shared__ __align__(16) float As[2][TI][PITCH];
    __shared__ __align__(16) float Bs[2][TJ][PITCH];   // holds NEGATED rows
    __shared__ float s_tr[TJ][TI + 1];                 // transpose staging
    __shared__ int   s_lab[B];
    __shared__ int   s_pbuf[512];
    __shared__ int   s_pcnt;
    __shared__ int   s_base;
    __shared__ float s_total;
    __shared__ int   s_count;

    const int tid = threadIdx.x;
    const int bid = blockIdx.x;

    for (int j = tid; j < B; j += NTHR) s_lab[j] = labels[j];
    if (tid == 0) { s_total = 0.0f; s_count = 0; s_pcnt = 0; }
    __syncthreads();

    // ---- phase A1: pair compaction (384*384 == 288 * 512 combos) -----------
#pragma unroll
    for (int e = 0; e < 2; e++) {
        int idx = bid * 512 + e * NTHR + tid;
        int i = idx / B, p = idx - i * B;
        if (p > i && s_lab[i] == s_lab[p]) {
            int slot = atomicAdd(&s_pcnt, 1);
            s_pbuf[slot] = (i << 16) | p;
        }
    }
    __syncthreads();
    if (tid == 0 && s_pcnt > 0) s_base = atomicAdd(&g_npairs, s_pcnt);
    __syncthreads();
    for (int j = tid; j < s_pcnt; j += NTHR) g_pairlist[s_base + j] = s_pbuf[j];

    // ---- phase A2: upper-triangle 32x16 dist tile + mirrored write ----------
    if (bid < NJOBS) {
        // job -> (ti, tj, half): tiles (ti<=tj) in row-major triangular order
        int t = bid >> 1;
        const int half = bid & 1;
        int ti = 0;
        while (t >= 12 - ti) { t -= 12 - ti; ti++; }
        const int tj = ti + t;
        const int i0 = ti * TI;
        const int j0 = tj * TI + half * TJ;

        const int lr = tid >> 4;                     // 0..15 (rows lr, lr+16)
        const int lc = tid & 15;                     // 0..15 (col)
        const int alr = tid >> 3;                    // 0..31, float4/thread
        const int alc = (tid & 7) * 4;
        const int blr = tid >> 4;                    // 0..15, float2/thread
        const int blc = (tid & 15) * 2;

        u64 acc0l = 0, acc0h = 0, acc1l = 0, acc1h = 0;

        // preload + store chunk 0
        float4 a4 = *(const float4*)&f[(i0 + alr) * D + alc];
        float2 b2 = *(const float2*)&f[(j0 + blr) * D + blc];
        *(float4*)&As[0][alr][alc] = a4;
        Bs[0][blr][blc]     = -b2.x;
        Bs[0][blr][blc + 1] = -b2.y;
        __syncthreads();

#pragma unroll
        for (int c = 0; c < D / TK; c++) {
            const int buf = c & 1;
            if (c < D / TK - 1) {
                const int kk = (c + 1) * TK;
                a4 = *(const float4*)&f[(i0 + alr) * D + kk + alc];
                b2 = *(const float2*)&f[(j0 + blr) * D + kk + blc];
            }
#pragma unroll
            for (int k4 = 0; k4 < TK / 4; k4++) {
                ulonglong2 nb = *(const ulonglong2*)&Bs[buf][lc][k4 * 4];
                ulonglong2 a0 = *(const ulonglong2*)&As[buf][lr][k4 * 4];
                ulonglong2 a1 = *(const ulonglong2*)&As[buf][lr + 16][k4 * 4];
                u64 d0, d1, d2, d3;
                ADD2(d0, a0.x, nb.x); FMA2(acc0l, d0);
                ADD2(d1, a0.y, nb.y); FMA2(acc0h, d1);
                ADD2(d2, a1.x, nb.x); FMA2(acc1l, d2);
                ADD2(d3, a1.y, nb.y); FMA2(acc1h, d3);
            }
            if (c < D / TK - 1) {
                const int nbuf = buf ^ 1;
                *(float4*)&As[nbuf][alr][alc] = a4;   // other buffer: no hazard
                Bs[nbuf][blr][blc]     = -b2.x;
                Bs[nbuf][blr][blc + 1] = -b2.y;
                __syncthreads();                      // one barrier per chunk
            }
        }

        float2 p0l = *(float2*)&acc0l, p0h = *(float2*)&acc0h;
        float2 p1l = *(float2*)&acc1l, p1h = *(float2*)&acc1h;
        float v0 = sqrtf(fmaxf((p0l.x + p0l.y) + (p0h.x + p0h.y), 1e-11f));
        float v1 = sqrtf(fmaxf((p1l.x + p1l.y) + (p1h.x + p1h.y), 1e-11f));

        // direct (coalesced) writes
        g_dist[(i0 + lr)      * B + j0 + lc] = v0;
        g_dist[(i0 + lr + 16) * B + j0 + lc] = v1;

        // mirror via smem transpose (coalesced rows; identical-value overlap
        // on diagonal tiles is a benign bitwise-equal race)
        s_tr[lc][lr]      = v0;
        s_tr[lc][lr + 16] = v1;
        __syncthreads();
        {
            const int r  = tid >> 5;          // 0..7
            const int cc = tid & 31;          // 0..31
            g_dist[(j0 + r)     * B + i0 + cc] = s_tr[r][cc];
            g_dist[(j0 + r + 8) * B + i0 + cc] = s_tr[r + 8][cc];
        }
    }

    grid_barrier();

    // ---- phase B: one warp per pair, batched loads + inlined gumbel --------
    const bool semi_mode = (epoch[0] > 3);
    const int lane  = tid & 31;
    const int gw    = bid * (NTHR / 32) + (tid >> 5);
    const int nwarp = gridDim.x * (NTHR / 32);
    const int np    = *(volatile int*)&g_npairs;

    float wsum = 0.0f;
    int   wcnt = 0;

    for (int q = gw; q < np; q += nwarp) {
        const int code = g_pairlist[q];
        const int i = code >> 16, p = code & 0xffff;
        const int li = s_lab[i];
        const float* drow = g_dist + i * B;
        const float dpos = drow[p];
        const uint32_t nbase = ((uint32_t)i * B + p) * B;

        // 1) batch all 12 candidate loads (independent -> MLP=12)
        float dv[B / 32];
#pragma unroll
        for (int s = 0; s < B / 32; s++) dv[s] = drow[s * 32 + lane];

        // 2) masks + gumbel at semi sites (inlined; chains overlap)
        float best = -3.0e38f;
        int   bidx = 0x7fffffff;
        bool  anyf = false;
#pragma unroll
        for (int s = 0; s < B / 32; s++) {
            const int k = s * 32 + lane;
            const float dik = dv[s];
            const bool neg = (s_lab[k] != li);
            const bool semi = semi_mode
                ? (neg && dik > dpos && dik < dpos + MARGIN) : neg;
            if (semi) {
                anyf = true;
                float base = semi_mode ? -logf(dik) : 0.0f;
                float sc = base + gumbel_at(nbase + k);
                if (sc > best || (sc == best && k < bidx)) { best = sc; bidx = k; }
            }
        }
        // warp argmax, first-index tie break (matches jnp.argmax)
#pragma unroll
        for (int off = 16; off; off >>= 1) {
            float ov = __shfl_down_sync(0xffffffffu, best, off);
            int   oi = __shfl_down_sync(0xffffffffu, bidx, off);
            if (ov > best || (ov == best && oi < bidx)) { best = ov; bidx = oi; }
        }
        const bool any = __any_sync(0xffffffffu, anyf);
        if (lane == 0 && any) {
            wsum += fmaxf(dpos - drow[bidx] + MARGIN, 0.0f);
            wcnt += 1;
        }
    }

    if (lane == 0 && wcnt > 0) {
        atomicAdd(&s_total, wsum);
        atomicAdd(&s_count, wcnt);
    }
    __syncthreads();
    if (tid == 0 && s_count > 0) {
        atomicAdd(&g_total, s_total);
        atomicAdd(&g_count, s_count);
    }

    // ---- finalize: last block writes the result & resets persistent state ---
    __threadfence();
    if (tid == 0) {
        if (atomicAdd(&g_done, 1u) == gridDim.x - 1) {
            float tot = atomicAdd(&g_total, 0.0f);   // atomic read-after-fence
            int   cnt = atomicAdd(&g_count, 0);
            out[0] = (cnt > 0) ? (tot / (float)cnt) : 0.0f;
            g_total  = 0.0f;
            g_count  = 0;
            g_npairs = 0;
            __threadfence();
            atomicExch(&g_done, 0u);
        }
    }
}

// ---- launch ------------------------------------------------------------------
extern "C" void kernel_launch(void* const* d_in, const int* in_sizes, int n_in,
                              void* d_out, int out_size) {
    const float* feat   = (const float*)d_in[0];
    const int*   labels = (const int*)d_in[1];
    const int*   epoch  = (const int*)d_in[2];
    float* out = (float*)d_out;

    k_fused<<<NBLK, NTHR>>>(feat, labels, epoch, out);
}

// round 14
// speedup vs baseline: 1.3367x; 1.3367x over previous
#include <cuda_runtime.h>
#include <cstdint>

// ---------------------------------------------------------------------------
// TripletLoss, single fused persistent kernel.
//   R12 logic; grid reshaped to 288 blocks x 512 threads with UNIFORM 32x16
//   half-tile jobs (2 blocks/SM guaranteed via __launch_bounds__(512,2)) so
//   two co-resident blocks hide each other's LDS/LDG/barrier stalls.
//   B=384, D=256, C=48. JAX-exact gumbel via threefry2x32 (partitionable,
//   bits = x0^x1, key=[0,42]) evaluated only at semi-hard sites.
// ---------------------------------------------------------------------------

#define B 384
#define D 256
#define MARGIN 0.2f
#define TINYF 1.17549435e-38f
#define NBLK 288
#define NTHR 512
#define TI 32                         // tile rows (i)
#define TJ 16                         // tile cols (j)
#define TK 32                         // K chunk
#define PITCH 36                      // floats; 144B rows, 16B-aligned
#define NPAIR_MAX ((B * (B - 1)) / 2)

typedef unsigned long long u64;

// packed f32x2 helpers (Blackwell sm_103a; ptxas never emits these from C++)
#define ADD2(out, a, b) \
    asm("add.rn.f32x2 %0, %1, %2;" : "=l"(out) : "l"(a), "l"(b))
#define FMA2(acc, d) \
    asm("fma.rn.f32x2 %0, %1, %1, %0;" : "+l"(acc) : "l"(d))

// ---- persistent device state (restored to initial values every run) -------
__device__ float    g_dist[B * B];
__device__ int      g_pairlist[NPAIR_MAX];
__device__ int      g_npairs = 0;
__device__ float    g_total  = 0.0f;
__device__ int      g_count  = 0;
__device__ unsigned g_done   = 0;
__device__ unsigned g_barcnt = 0;
__device__ volatile unsigned g_sense = 0;

// ---- threefry2x32, JAX schedule, key = [0, 42] -----------------------------
__device__ __forceinline__ uint32_t rotl32(uint32_t x, int d) {
    return __funnelshift_l(x, x, d);
}

__device__ __forceinline__ float gumbel_at(uint32_t n) {
    // counter = (0, n) since n < 384^3 < 2^32 ; key = [0, 42]
    const uint32_t k0 = 0u, k1 = 42u;
    const uint32_t k2 = k0 ^ k1 ^ 0x1BD11BDAu;
    uint32_t x0 = 0u + k0, x1 = n + k1;
#define TF_RND(r) { x0 += x1; x1 = rotl32(x1, (r)); x1 ^= x0; }
    TF_RND(13) TF_RND(15) TF_RND(26) TF_RND(6)
    x0 += k1; x1 += k2 + 1u;
    TF_RND(17) TF_RND(29) TF_RND(16) TF_RND(24)
    x0 += k2; x1 += k0 + 2u;
    TF_RND(13) TF_RND(15) TF_RND(26) TF_RND(6)
    x0 += k0; x1 += k1 + 3u;
    TF_RND(17) TF_RND(29) TF_RND(16) TF_RND(24)
    x0 += k1; x1 += k2 + 4u;
    TF_RND(13) TF_RND(15) TF_RND(26) TF_RND(6)
    x0 += k2; x1 += k0 + 5u;
#undef TF_RND
    uint32_t bits = x0 ^ x1;   // partitionable 32-bit draw
    float f = __uint_as_float((bits >> 9) | 0x3f800000u) - 1.0f;
    float u = fmaxf(TINYF, f + TINYF);
    return -logf(-logf(u));
}

// ---- sense-reversing grid barrier (288 blocks, 2/SM guaranteed, one wave) --
__device__ __forceinline__ void grid_barrier() {
    __syncthreads();
    __threadfence();
    if (threadIdx.x == 0) {
        unsigned s = g_sense;
        if (atomicAdd(&g_barcnt, 1u) == gridDim.x - 1) {
            atomicExch(&g_barcnt, 0u);
            __threadfence();
            g_sense = s ^ 1u;
        } else {
            while (g_sense == s) { }
        }
    }
    __syncthreads();
}

// ---- the fused kernel --------------------------------------------------------
__global__ void __launch_bounds__(NTHR, 2)
k_fused(const float* __restrict__ f, const int* __restrict__ labels,
        const int* __restrict__ epoch, float* __restrict__ out) {
    __shared__ __align__(16) float As[2][TI][PITCH];
    __shared__ __align__(16) float Bs[2][TJ][PITCH];   // holds NEGATED rows
    __shared__ int   s_lab[B];
    __shared__ int   s_pbuf[512];
    __shared__ int   s_pcnt;
    __shared__ int   s_base;
    __shared__ float s_total;
    __shared__ int   s_count;

    const int tid = threadIdx.x;
    const int bid = blockIdx.x;

    if (tid < B) s_lab[tid] = labels[tid];
    if (tid == 0) { s_total = 0.0f; s_count = 0; s_pcnt = 0; }
    __syncthreads();

    // ---- phase A1: pair compaction (384*384 == 288 * 512 combos) -----------
    {
        int idx = bid * 512 + tid;
        int i = idx / B, p = idx - i * B;
        if (p > i && s_lab[i] == s_lab[p]) {
            int slot = atomicAdd(&s_pcnt, 1);
            s_pbuf[slot] = (i << 16) | p;
        }
    }
    __syncthreads();
    if (tid == 0 && s_pcnt > 0) s_base = atomicAdd(&g_npairs, s_pcnt);
    __syncthreads();
    if (tid < s_pcnt) g_pairlist[s_base + tid] = s_pbuf[tid];

    // ---- phase A2: 32x16 dist half-tile, double-buffered, f32x2 math -------
    {
        const int t    = bid >> 1;                   // tile 0..143 (12x12)
        const int half = bid & 1;
        const int i0 = (t / 12) * TI;
        const int j0 = (t % 12) * TI + half * TJ;

        const int r  = tid >> 4;                     // 0..31 output row
        const int cc = tid & 15;                     // 0..15 output col
        const int alr = tid >> 4;                    // A loader: row, float2
        const int alc = (tid & 15) * 2;
        const int blr = tid >> 5;                    // B loader: row, scalar
        const int blc = tid & 31;

        u64 accl = 0, acch = 0;                      // packed f32x2 accums

        // preload + store chunk 0
        float2 a2 = *(const float2*)&f[(i0 + alr) * D + alc];
        float  b1 = f[(j0 + blr) * D + blc];
        *(float2*)&As[0][alr][alc] = a2;
        Bs[0][blr][blc] = -b1;                       // negated: diff = add
        __syncthreads();

#pragma unroll
        for (int c = 0; c < D / TK; c++) {
            const int buf = c & 1;
            if (c < D / TK - 1) {
                const int kk = (c + 1) * TK;
                a2 = *(const float2*)&f[(i0 + alr) * D + kk + alc];
                b1 = f[(j0 + blr) * D + kk + blc];
            }
#pragma unroll
            for (int k4 = 0; k4 < TK / 4; k4++) {
                ulonglong2 nb = *(const ulonglong2*)&Bs[buf][cc][k4 * 4];
                ulonglong2 av = *(const ulonglong2*)&As[buf][r][k4 * 4];
                u64 d0, d1;
                ADD2(d0, av.x, nb.x); FMA2(accl, d0);
                ADD2(d1, av.y, nb.y); FMA2(acch, d1);
            }
            if (c < D / TK - 1) {
                const int nbuf = buf ^ 1;
                *(float2*)&As[nbuf][alr][alc] = a2;  // other buffer: no hazard
                Bs[nbuf][blr][blc] = -b1;
                __syncthreads();                     // one barrier per chunk
            }
        }

        float2 pl = *(float2*)&accl, ph = *(float2*)&acch;
        float s = (pl.x + pl.y) + (ph.x + ph.y);
        g_dist[(i0 + r) * B + j0 + cc] = sqrtf(fmaxf(s, 1e-11f));
    }

    grid_barrier();

    // ---- phase B: one warp per pair, batched loads + inlined gumbel --------
    const bool semi_mode = (epoch[0] > 3);
    const int lane  = tid & 31;
    const int gw    = bid * (NTHR / 32) + (tid >> 5);
    const int nwarp = gridDim.x * (NTHR / 32);
    const int np    = *(volatile int*)&g_npairs;

    float wsum = 0.0f;
    int   wcnt = 0;

    for (int q = gw; q < np; q += nwarp) {
        const int code = g_pairlist[q];
        const int i = code >> 16, p = code & 0xffff;
        const int li = s_lab[i];
        const float* drow = g_dist + i * B;
        const float dpos = drow[p];
        const uint32_t nbase = ((uint32_t)i * B + p) * B;

        // 1) batch all 12 candidate loads (independent -> MLP=12)
        float dv[B / 32];
#pragma unroll
        for (int s = 0; s < B / 32; s++) dv[s] = drow[s * 32 + lane];

        // 2) masks + gumbel at semi sites (inlined; chains overlap)
        float best = -3.0e38f;
        int   bidx = 0x7fffffff;
        bool  anyf = false;
#pragma unroll
        for (int s = 0; s < B / 32; s++) {
            const int k = s * 32 + lane;
            const float dik = dv[s];
            const bool neg = (s_lab[k] != li);
            const bool semi = semi_mode
                ? (neg && dik > dpos && dik < dpos + MARGIN) : neg;
            if (semi) {
                anyf = true;
                float base = semi_mode ? -logf(dik) : 0.0f;
                float sc = base + gumbel_at(nbase + k);
                if (sc > best || (sc == best && k < bidx)) { best = sc; bidx = k; }
            }
        }
        // warp argmax, first-index tie break (matches jnp.argmax)
#pragma unroll
        for (int off = 16; off; off >>= 1) {
            float ov = __shfl_down_sync(0xffffffffu, best, off);
            int   oi = __shfl_down_sync(0xffffffffu, bidx, off);
            if (ov > best || (ov == best && oi < bidx)) { best = ov; bidx = oi; }
        }
        const bool any = __any_sync(0xffffffffu, anyf);
        if (lane == 0 && any) {
            wsum += fmaxf(dpos - drow[bidx] + MARGIN, 0.0f);
            wcnt += 1;
        }
    }

    if (lane == 0 && wcnt > 0) {
        atomicAdd(&s_total, wsum);
        atomicAdd(&s_count, wcnt);
    }
    __syncthreads();
    if (tid == 0 && s_count > 0) {
        atomicAdd(&g_total, s_total);
        atomicAdd(&g_count, s_count);
    }

    // ---- finalize: last block writes the result & resets persistent state ---
    __threadfence();
    if (tid == 0) {
        if (atomicAdd(&g_done, 1u) == gridDim.x - 1) {
            float tot = atomicAdd(&g_total, 0.0f);   // atomic read-after-fence
            int   cnt = atomicAdd(&g_count, 0);
            out[0] = (cnt > 0) ? (tot / (float)cnt) : 0.0f;
            g_total  = 0.0f;
            g_count  = 0;
            g_npairs = 0;
            __threadfence();
            atomicExch(&g_done, 0u);
        }
    }
}

// ---- launch ------------------------------------------------------------------
extern "C" void kernel_launch(void* const* d_in, const int* in_sizes, int n_in,
                              void* d_out, int out_size) {
    const float* feat   = (const float*)d_in[0];
    const int*   labels = (const int*)d_in[1];
    const int*   epoch  = (const int*)d_in[2];
    float* out = (float*)d_out;

    k_fused<<<NBLK, NTHR>>>(feat, labels, epoch, out);
}

// round 15
// speedup vs baseline: 1.5783x; 1.1807x over previous
#include <cuda_runtime.h>
#include <cstdint>

// ---------------------------------------------------------------------------
// TripletLoss, single fused persistent kernel (R12 skeleton, 144x512).
//   A2: TK=64 chunks (3 intermediate syncs), float4 loads, writes dist and
//       -log(dist). Phase B: batched dv+nlogd loads (MLP=24), inlined gumbel.
//   B=384, D=256, C=48. JAX-exact gumbel via threefry2x32 (partitionable,
//   bits = x0^x1, key=[0,42]) evaluated only at semi-hard sites.
// ---------------------------------------------------------------------------

#define B 384
#define D 256
#define MARGIN 0.2f
#define TINYF 1.17549435e-38f
#define NBLK 144
#define NTHR 512
#define TILE 32
#define TK 64
#define PITCH 68                      // floats; 272B rows, 16B-aligned float4
#define NPAIR_MAX ((B * (B - 1)) / 2)

typedef unsigned long long u64;

// packed f32x2 helpers (Blackwell sm_103a; ptxas never emits these from C++)
#define ADD2(out, a, b) \
    asm("add.rn.f32x2 %0, %1, %2;" : "=l"(out) : "l"(a), "l"(b))
#define FMA2(acc, d) \
    asm("fma.rn.f32x2 %0, %1, %1, %0;" : "+l"(acc) : "l"(d))

// ---- persistent device state (restored to initial values every run) -------
__device__ float    g_dist[B * B];
__device__ float    g_nlogd[B * B];   // -log(dist), computed in A2
__device__ int      g_pairlist[NPAIR_MAX];
__device__ int      g_npairs = 0;
__device__ float    g_total  = 0.0f;
__device__ int      g_count  = 0;
__device__ unsigned g_done   = 0;
__device__ unsigned g_barcnt = 0;
__device__ volatile unsigned g_sense = 0;

// ---- threefry2x32, JAX schedule, key = [0, 42] -----------------------------
__device__ __forceinline__ uint32_t rotl32(uint32_t x, int d) {
    return __funnelshift_l(x, x, d);
}

__device__ __forceinline__ float gumbel_at(uint32_t n) {
    // counter = (0, n) since n < 384^3 < 2^32 ; key = [0, 42]
    const uint32_t k0 = 0u, k1 = 42u;
    const uint32_t k2 = k0 ^ k1 ^ 0x1BD11BDAu;
    uint32_t x0 = 0u + k0, x1 = n + k1;
#define TF_RND(r) { x0 += x1; x1 = rotl32(x1, (r)); x1 ^= x0; }
    TF_RND(13) TF_RND(15) TF_RND(26) TF_RND(6)
    x0 += k1; x1 += k2 + 1u;
    TF_RND(17) TF_RND(29) TF_RND(16) TF_RND(24)
    x0 += k2; x1 += k0 + 2u;
    TF_RND(13) TF_RND(15) TF_RND(26) TF_RND(6)
    x0 += k0; x1 += k1 + 3u;
    TF_RND(17) TF_RND(29) TF_RND(16) TF_RND(24)
    x0 += k1; x1 += k2 + 4u;
    TF_RND(13) TF_RND(15) TF_RND(26) TF_RND(6)
    x0 += k2; x1 += k0 + 5u;
#undef TF_RND
    uint32_t bits = x0 ^ x1;   // partitionable 32-bit draw
    float f = __uint_as_float((bits >> 9) | 0x3f800000u) - 1.0f;
    float u = fmaxf(TINYF, f + TINYF);
    return -logf(-logf(u));
}

// ---- sense-reversing grid barrier (144 blocks <= 148 SMs, 1/SM resident) ---
__device__ __forceinline__ void grid_barrier() {
    __syncthreads();
    __threadfence();
    if (threadIdx.x == 0) {
        unsigned s = g_sense;
        if (atomicAdd(&g_barcnt, 1u) == gridDim.x - 1) {
            atomicExch(&g_barcnt, 0u);
            __threadfence();
            g_sense = s ^ 1u;
        } else {
            while (g_sense == s) { }
        }
    }
    __syncthreads();
}

// ---- the fused kernel --------------------------------------------------------
__global__ void __launch_bounds__(NTHR)
k_fused(const float* __restrict__ f, const int* __restrict__ labels,
        const int* __restrict__ epoch, float* __restrict__ out) {
    __shared__ __align__(16) float As[2][TILE][PITCH];
    __shared__ __align__(16) float Bs[2][TILE][PITCH];   // holds NEGATED rows
    __shared__ int   s_lab[B];
    __shared__ int   s_pbuf[128];
    __shared__ int   s_pcnt;
    __shared__ float s_total;
    __shared__ int   s_count;

    const int tid = threadIdx.x;
    const int bid = blockIdx.x;

    if (tid < B) s_lab[tid] = labels[tid];
    if (tid == 0) { s_total = 0.0f; s_count = 0; s_pcnt = 0; }
    __syncthreads();

    // ---- phase A1: pair compaction, smem-local then one global atomic ------
#pragma unroll
    for (int e = 0; e < 2; e++) {
        int idx = bid * 1024 + e * NTHR + tid;
        int i = idx / B, p = idx - i * B;
        if (p > i && s_lab[i] == s_lab[p]) {
            int slot = atomicAdd(&s_pcnt, 1);
            s_pbuf[slot] = (i << 16) | p;
        }
    }
    __syncthreads();
    {
        __shared__ int s_base;
        if (tid == 0 && s_pcnt > 0) s_base = atomicAdd(&g_npairs, s_pcnt);
        __syncthreads();
        if (tid < s_pcnt) g_pairlist[s_base + tid] = s_pbuf[tid];
    }

    // ---- phase A2: 32x32 dist tile, TK=64 double-buffered, f32x2 math ------
    {
        const int by = bid / 12, bx = bid % 12;
        const int i0 = by * TILE, j0 = bx * TILE;
        const int lr = tid >> 5;          // compute rows lr and lr+16
        const int lc = tid & 31;          // compute col
        const int l4r = tid >> 4;         // loader row 0..31
        const int l4c = (tid & 15) * 4;   // loader col (float4)

        u64 acc0l = 0, acc0h = 0, acc1l = 0, acc1h = 0;   // packed f32x2 accs

        // preload + store chunk 0 (one float4 per thread per matrix)
        float4 a4 = *(const float4*)&f[(i0 + l4r) * D + l4c];
        float4 b4 = *(const float4*)&f[(j0 + l4r) * D + l4c];
        *(float4*)&As[0][l4r][l4c] = a4;
        {
            float4 nb4; nb4.x = -b4.x; nb4.y = -b4.y; nb4.z = -b4.z; nb4.w = -b4.w;
            *(float4*)&Bs[0][l4r][l4c] = nb4;
        }
        __syncthreads();

#pragma unroll
        for (int c = 0; c < D / TK; c++) {
            const int buf = c & 1;
            if (c < D / TK - 1) {
                const int kk = (c + 1) * TK;
                a4 = *(const float4*)&f[(i0 + l4r) * D + kk + l4c];
                b4 = *(const float4*)&f[(j0 + l4r) * D + kk + l4c];
            }
#pragma unroll
            for (int k4 = 0; k4 < TK / 4; k4++) {
                ulonglong2 nb = *(const ulonglong2*)&Bs[buf][lc][k4 * 4];
                ulonglong2 a0 = *(const ulonglong2*)&As[buf][lr][k4 * 4];
                ulonglong2 a1 = *(const ulonglong2*)&As[buf][lr + 16][k4 * 4];
                u64 d0, d1, d2, d3;
                ADD2(d0, a0.x, nb.x); FMA2(acc0l, d0);
                ADD2(d1, a0.y, nb.y); FMA2(acc0h, d1);
                ADD2(d2, a1.x, nb.x); FMA2(acc1l, d2);
                ADD2(d3, a1.y, nb.y); FMA2(acc1h, d3);
            }
            if (c < D / TK - 1) {
                const int nbuf = buf ^ 1;
                *(float4*)&As[nbuf][l4r][l4c] = a4;   // other buffer: no hazard
                float4 nb4; nb4.x = -b4.x; nb4.y = -b4.y; nb4.z = -b4.z; nb4.w = -b4.w;
                *(float4*)&Bs[nbuf][l4r][l4c] = nb4;
                __syncthreads();                      // one barrier per chunk
            }
        }

        float2 p0l = *(float2*)&acc0l, p0h = *(float2*)&acc0h;
        float2 p1l = *(float2*)&acc1l, p1h = *(float2*)&acc1h;
        float s0 = (p0l.x + p0l.y) + (p0h.x + p0h.y);
        float s1 = (p1l.x + p1l.y) + (p1h.x + p1h.y);
        float v0 = sqrtf(fmaxf(s0, 1e-11f));
        float v1 = sqrtf(fmaxf(s1, 1e-11f));
        g_dist[(i0 + lr)      * B + j0 + lc] = v0;
        g_dist[(i0 + lr + 16) * B + j0 + lc] = v1;
        g_nlogd[(i0 + lr)      * B + j0 + lc] = -logf(v0);
        g_nlogd[(i0 + lr + 16) * B + j0 + lc] = -logf(v1);
    }

    grid_barrier();

    // ---- phase B: one warp per pair, batched loads + inlined gumbel --------
    const bool semi_mode = (epoch[0] > 3);
    const int lane  = tid & 31;
    const int gw    = bid * (NTHR / 32) + (tid >> 5);
    const int nwarp = gridDim.x * (NTHR / 32);
    const int np    = *(volatile int*)&g_npairs;

    float wsum = 0.0f;
    int   wcnt = 0;

    for (int q = gw; q < np; q += nwarp) {
        const int code = g_pairlist[q];
        const int i = code >> 16, p = code & 0xffff;
        const int li = s_lab[i];
        const float* drow  = g_dist  + i * B;
        const float* nlrow = g_nlogd + i * B;
        const float dpos = drow[p];
        const uint32_t nbase = ((uint32_t)i * B + p) * B;

        // 1) batch candidate dist + nlog loads (independent -> MLP=24)
        float dv[B / 32], nlv[B / 32];
#pragma unroll
        for (int s = 0; s < B / 32; s++) dv[s]  = drow[s * 32 + lane];
#pragma unroll
        for (int s = 0; s < B / 32; s++) nlv[s] = nlrow[s * 32 + lane];

        // 2) masks + gumbel at semi sites (inlined; chains overlap)
        float best = -3.0e38f;
        int   bidx = 0x7fffffff;
        bool  anyf = false;
#pragma unroll
        for (int s = 0; s < B / 32; s++) {
            const int k = s * 32 + lane;
            const float dik = dv[s];
            const bool neg = (s_lab[k] != li);
            const bool semi = semi_mode
                ? (neg && dik > dpos && dik < dpos + MARGIN) : neg;
            if (semi) {
                anyf = true;
                float base = semi_mode ? nlv[s] : 0.0f;
                float sc = base + gumbel_at(nbase + k);
                if (sc > best || (sc == best && k < bidx)) { best = sc; bidx = k; }
            }
        }
        // warp argmax, first-index tie break (matches jnp.argmax)
#pragma unroll
        for (int off = 16; off; off >>= 1) {
            float ov = __shfl_down_sync(0xffffffffu, best, off);
            int   oi = __shfl_down_sync(0xffffffffu, bidx, off);
            if (ov > best || (ov == best && oi < bidx)) { best = ov; bidx = oi; }
        }
        const bool any = __any_sync(0xffffffffu, anyf);
        if (lane == 0 && any) {
            wsum += fmaxf(dpos - drow[bidx] + MARGIN, 0.0f);
            wcnt += 1;
        }
    }

    if (lane == 0 && wcnt > 0) {
        atomicAdd(&s_total, wsum);
        atomicAdd(&s_count, wcnt);
    }
    __syncthreads();
    if (tid == 0 && s_count > 0) {
        atomicAdd(&g_total, s_total);
        atomicAdd(&g_count, s_count);
    }

    // ---- finalize: last block writes the result & resets persistent state ---
    __threadfence();
    if (tid == 0) {
        if (atomicAdd(&g_done, 1u) == gridDim.x - 1) {
            float tot = atomicAdd(&g_total, 0.0f);   // atomic read-after-fence
            int   cnt = atomicAdd(&g_count, 0);
            out[0] = (cnt > 0) ? (tot / (float)cnt) : 0.0f;
            g_total  = 0.0f;
            g_count  = 0;
            g_npairs = 0;
            __threadfence();
            atomicExch(&g_done, 0u);
        }
    }
}

// ---- launch ------------------------------------------------------------------
extern "C" void kernel_launch(void* const* d_in, const int* in_sizes, int n_in,
                              void* d_out, int out_size) {
    const float* feat   = (const float*)d_in[0];
    const int*   labels = (const int*)d_in[1];
    const int*   epoch  = (const int*)d_in[2];
    float* out = (float*)d_out;

    k_fused<<<NBLK, NTHR>>>(feat, labels, epoch, out);
}